// round 1
// baseline (speedup 1.0000x reference)
#include <cuda_runtime.h>

// Problem: out[b,s,o] = sum_d x[b,s,d]*W[o,d] + bias[o] + 2*sum_r (sum_d x*A[r,d]) * B[o,r]
// Fold: W_eff = W + 2 * B @ A  -> out = X @ W_eff^T + bias  (single NT GEMM)
// X: [M=16384, K=1024] row-major, W_eff: [N=1024, K=1024] row-major.

#define M_TOTAL 16384
#define N_DIM   1024
#define K_DIM   1024
#define R_RANK  16

#define BM 128
#define BN 128
#define BK 16
#define TM 8
#define TN 8
// 256 threads = 16x16 thread tile grid

__device__ float g_Weff[N_DIM * K_DIM];

// ---------------------------------------------------------------------------
// Kernel 1: W_eff[o,k] = W[o,k] + 2 * sum_r B[o,r] * A[r,k]
// grid = N_DIM blocks, 256 threads. Tiny (33 MFLOP, ~8MB traffic).
// ---------------------------------------------------------------------------
__global__ void build_weff_kernel(const float* __restrict__ W,
                                  const float* __restrict__ A,
                                  const float* __restrict__ Bm) {
    const int o = blockIdx.x;
    const int t = threadIdx.x;

    __shared__ float brow[R_RANK];
    if (t < R_RANK) brow[t] = 2.0f * Bm[o * R_RANK + t];
    __syncthreads();

    // 1024 columns, 256 threads, float4 per thread
    for (int k4 = t * 4; k4 < K_DIM; k4 += blockDim.x * 4) {
        float4 w = *(const float4*)&W[o * K_DIM + k4];
        float acc0 = w.x, acc1 = w.y, acc2 = w.z, acc3 = w.w;
        #pragma unroll
        for (int r = 0; r < R_RANK; r++) {
            float br = brow[r];
            const float4 a = *(const float4*)&A[r * K_DIM + k4];
            acc0 = fmaf(br, a.x, acc0);
            acc1 = fmaf(br, a.y, acc1);
            acc2 = fmaf(br, a.z, acc2);
            acc3 = fmaf(br, a.w, acc3);
        }
        float4 outv = make_float4(acc0, acc1, acc2, acc3);
        *(float4*)&g_Weff[o * K_DIM + k4] = outv;
    }
}

// ---------------------------------------------------------------------------
// Kernel 2: out = X @ W_eff^T + bias.  128x128x16 tile, 8x8 per thread.
// ---------------------------------------------------------------------------
__global__ __launch_bounds__(256) void sgemm_nt_bias_kernel(
    const float* __restrict__ X,
    const float* __restrict__ bias,
    float* __restrict__ Out) {
    __shared__ float As[BK][BM];  // x tile, transposed (k-major -> m contiguous)
    __shared__ float Bs[BK][BN];  // W_eff tile, transposed

    const int tid = threadIdx.x;
    const int block_m = blockIdx.y * BM;
    const int block_n = blockIdx.x * BN;

    // compute-thread micro-tile origin
    const int tm = (tid / 16) * TM;  // 0..120
    const int tn = (tid % 16) * TN;  // 0..120

    float acc[TM][TN];
    #pragma unroll
    for (int i = 0; i < TM; i++)
        #pragma unroll
        for (int j = 0; j < TN; j++)
            acc[i][j] = 0.0f;

    const float* xbase = X + (long)block_m * K_DIM;
    const float* wbase = g_Weff + (long)block_n * K_DIM;

    for (int k0 = 0; k0 < K_DIM; k0 += BK) {
        // Load 128 rows x 16 cols per matrix = 512 float4; 2 float4/thread/matrix.
        #pragma unroll
        for (int i = 0; i < 2; i++) {
            int idx = tid + i * 256;        // 0..511
            int row = idx >> 2;             // 0..127
            int c4  = (idx & 3) << 2;       // 0,4,8,12
            float4 v = *(const float4*)&xbase[row * K_DIM + k0 + c4];
            As[c4 + 0][row] = v.x;
            As[c4 + 1][row] = v.y;
            As[c4 + 2][row] = v.z;
            As[c4 + 3][row] = v.w;
            float4 w = *(const float4*)&wbase[row * K_DIM + k0 + c4];
            Bs[c4 + 0][row] = w.x;
            Bs[c4 + 1][row] = w.y;
            Bs[c4 + 2][row] = w.z;
            Bs[c4 + 3][row] = w.w;
        }
        __syncthreads();

        #pragma unroll
        for (int k = 0; k < BK; k++) {
            float ar[TM], br[TN];
            // vector loads from shared (broadcast-friendly)
            *(float4*)&ar[0] = *(const float4*)&As[k][tm];
            *(float4*)&ar[4] = *(const float4*)&As[k][tm + 4];
            *(float4*)&br[0] = *(const float4*)&Bs[k][tn];
            *(float4*)&br[4] = *(const float4*)&Bs[k][tn + 4];
            #pragma unroll
            for (int i = 0; i < TM; i++)
                #pragma unroll
                for (int j = 0; j < TN; j++)
                    acc[i][j] = fmaf(ar[i], br[j], acc[i][j]);
        }
        __syncthreads();
    }

    // Epilogue: add bias, vectorized stores
    float bvals[TN];
    *(float4*)&bvals[0] = *(const float4*)&bias[block_n + tn];
    *(float4*)&bvals[4] = *(const float4*)&bias[block_n + tn + 4];

    #pragma unroll
    for (int i = 0; i < TM; i++) {
        float* orow = Out + (long)(block_m + tm + i) * N_DIM + block_n + tn;
        float4 o0 = make_float4(acc[i][0] + bvals[0], acc[i][1] + bvals[1],
                                acc[i][2] + bvals[2], acc[i][3] + bvals[3]);
        float4 o1 = make_float4(acc[i][4] + bvals[4], acc[i][5] + bvals[5],
                                acc[i][6] + bvals[6], acc[i][7] + bvals[7]);
        *(float4*)&orow[0] = o0;
        *(float4*)&orow[4] = o1;
    }
}

// ---------------------------------------------------------------------------
// Launch
// inputs (metadata order): x [4,4096,1024] f32, W [1024,1024] f32,
//                          b [1024] f32, A [16,1024] f32, B [1024,16] f32
// output: [4,4096,1024] f32
// ---------------------------------------------------------------------------
extern "C" void kernel_launch(void* const* d_in, const int* in_sizes, int n_in,
                              void* d_out, int out_size) {
    const float* x  = (const float*)d_in[0];
    const float* W  = (const float*)d_in[1];
    const float* b  = (const float*)d_in[2];
    const float* A  = (const float*)d_in[3];
    const float* Bm = (const float*)d_in[4];
    float* out = (float*)d_out;

    build_weff_kernel<<<N_DIM, 256>>>(W, A, Bm);

    dim3 grid(N_DIM / BN, M_TOTAL / BM);  // (8, 128)
    sgemm_nt_bias_kernel<<<grid, 256>>>(x, b, out);
}

// round 3
// speedup vs baseline: 2.8222x; 2.8222x over previous
#include <cuda_runtime.h>
#include <cuda_bf16.h>
#include <cstdint>

// out = X @ W_eff^T + bias, W_eff = W + 2*B@A
// bf16 split-precision GEMM on tensor cores via mma.sync (base sm_103 target —
// tcgen05 is rejected by the harness's non-'a' PTX target).
// err model: drop xl*wl term -> ~eps_bf16^2 ~ 1.5e-5 relative.

#define M_TOTAL 16384
#define N_DIM   1024
#define K_DIM   1024
#define R_RANK  16

#define BM 128
#define BN 128
#define BK 64
#define NCHUNK (K_DIM / BK)   // 16

// stage layout (bytes): four 128x64 bf16 tiles of 16KB
#define STG_XHI 0
#define STG_XLO 16384
#define STG_WHI 32768
#define STG_WLO 49152
#define STAGE_BYTES 65536
#define SMEM_BYTES (2 * STAGE_BYTES)   // 128KB double buffer

__device__ __nv_bfloat16 g_Whi[N_DIM * K_DIM];
__device__ __nv_bfloat16 g_Wlo[N_DIM * K_DIM];
__device__ __nv_bfloat16 g_Xhi[M_TOTAL * K_DIM];
__device__ __nv_bfloat16 g_Xlo[M_TOTAL * K_DIM];

// ---------------- PTX helpers ----------------
__device__ __forceinline__ uint32_t smem_u32(const void* p) {
    uint32_t a;
    asm("{ .reg .u64 t; cvta.to.shared.u64 t, %1; cvt.u32.u64 %0, t; }" : "=r"(a) : "l"(p));
    return a;
}

#define CP_ASYNC16(dst, src) \
    asm volatile("cp.async.cg.shared.global [%0], [%1], 16;" :: "r"(dst), "l"(src))
#define CP_COMMIT() asm volatile("cp.async.commit_group;" ::: "memory")
#define CP_WAIT1()  asm volatile("cp.async.wait_group 1;" ::: "memory")
#define CP_WAIT0()  asm volatile("cp.async.wait_group 0;" ::: "memory")

#define LDSM_X4(r0, r1, r2, r3, addr) \
    asm volatile("ldmatrix.sync.aligned.m8n8.x4.shared.b16 {%0,%1,%2,%3}, [%4];" \
                 : "=r"(r0), "=r"(r1), "=r"(r2), "=r"(r3) : "r"(addr))

#define MMA_BF16(d, a, b) \
    asm volatile("mma.sync.aligned.m16n8k16.row.col.f32.bf16.bf16.f32 " \
                 "{%0,%1,%2,%3}, {%4,%5,%6,%7}, {%8,%9}, {%0,%1,%2,%3};" \
                 : "+f"((d)[0]), "+f"((d)[1]), "+f"((d)[2]), "+f"((d)[3]) \
                 : "r"((a)[0]), "r"((a)[1]), "r"((a)[2]), "r"((a)[3]), \
                   "r"((b)[0]), "r"((b)[1]))

// pack bf16x2 {low=l, high=h}
__device__ __forceinline__ uint32_t cvt2bf16(float l, float h) {
    uint32_t r;
    asm("cvt.rn.bf16x2.f32 %0, %1, %2;" : "=r"(r) : "f"(h), "f"(l));
    return r;
}

// split float4 -> bf16x2 hi pair + lo pair
__device__ __forceinline__ void split4(float4 v, uint32_t& hi01, uint32_t& hi23,
                                       uint32_t& lo01, uint32_t& lo23) {
    hi01 = cvt2bf16(v.x, v.y);
    hi23 = cvt2bf16(v.z, v.w);
    float h0 = __uint_as_float(hi01 << 16), h1 = __uint_as_float(hi01 & 0xffff0000u);
    float h2 = __uint_as_float(hi23 << 16), h3 = __uint_as_float(hi23 & 0xffff0000u);
    lo01 = cvt2bf16(v.x - h0, v.y - h1);
    lo23 = cvt2bf16(v.z - h2, v.w - h3);
}

// ---------------------------------------------------------------------------
// Prep 1: W_eff = W + 2*B@A, split bf16 hi/lo.
// ---------------------------------------------------------------------------
__global__ void build_weff_split_kernel(const float* __restrict__ W,
                                        const float* __restrict__ A,
                                        const float* __restrict__ Bm) {
    const int o = blockIdx.x;
    const int t = threadIdx.x;
    __shared__ float brow[R_RANK];
    if (t < R_RANK) brow[t] = 2.0f * Bm[o * R_RANK + t];
    __syncthreads();

    for (int k4 = t * 4; k4 < K_DIM; k4 += blockDim.x * 4) {
        float4 w = *(const float4*)&W[o * K_DIM + k4];
        float v[4] = {w.x, w.y, w.z, w.w};
        #pragma unroll
        for (int r = 0; r < R_RANK; r++) {
            float br = brow[r];
            const float4 a = *(const float4*)&A[r * K_DIM + k4];
            v[0] = fmaf(br, a.x, v[0]); v[1] = fmaf(br, a.y, v[1]);
            v[2] = fmaf(br, a.z, v[2]); v[3] = fmaf(br, a.w, v[3]);
        }
        uint32_t hi01, hi23, lo01, lo23;
        split4(make_float4(v[0], v[1], v[2], v[3]), hi01, hi23, lo01, lo23);
        *(uint2*)&g_Whi[o * K_DIM + k4] = make_uint2(hi01, hi23);
        *(uint2*)&g_Wlo[o * K_DIM + k4] = make_uint2(lo01, lo23);
    }
}

// ---------------------------------------------------------------------------
// Prep 2: split X fp32 -> bf16 hi/lo.
// ---------------------------------------------------------------------------
__global__ __launch_bounds__(256) void split_x_kernel(const float* __restrict__ X) {
    const size_t i4 = ((size_t)blockIdx.x * 256 + threadIdx.x) * 4;
    float4 v = *(const float4*)&X[i4];
    uint32_t hi01, hi23, lo01, lo23;
    split4(v, hi01, hi23, lo01, lo23);
    *(uint2*)&g_Xhi[i4] = make_uint2(hi01, hi23);
    *(uint2*)&g_Xlo[i4] = make_uint2(lo01, lo23);
}

// ---------------------------------------------------------------------------
// Main GEMM: 128x128 CTA tile, 512 threads, warp tile 32x32, bf16 split (3 mma).
// ---------------------------------------------------------------------------
__global__ __launch_bounds__(512) void lora_gemm_mma_kernel(
    const float* __restrict__ bias,
    float* __restrict__ Out) {
    extern __shared__ char smem[];
    const uint32_t sbase = smem_u32(smem);
    const int tid = threadIdx.x;
    const int lane = tid & 31;
    const int wid = tid >> 5;          // 0..15
    const int wm = wid & 3;            // 4 warps along M (32 rows each)
    const int wn = wid >> 2;           // 4 warps along N (32 cols each)

    const int block_m = blockIdx.y * BM;
    const int block_n = blockIdx.x * BN;

    // ---- cp.async plan: 8 x 16B per thread per stage ----
    uint32_t cp_dst[8];
    const __nv_bfloat16* cp_src[8];
    #pragma unroll
    for (int i = 0; i < 8; i++) {
        int idx = tid + i * 512;           // 0..4095
        int tile = idx >> 10;              // 0:Xhi 1:Xlo 2:Whi 3:Wlo
        int r   = (idx & 1023) >> 3;       // 0..127
        int c16 = idx & 7;                 // 16B chunk in 128B row
        uint32_t off = (uint32_t)(r * 128 + ((c16 * 16) ^ ((r & 7) * 16)));
        const __nv_bfloat16* g;
        int grow;
        if (tile == 0)      { g = g_Xhi; grow = block_m + r; off += STG_XHI; }
        else if (tile == 1) { g = g_Xlo; grow = block_m + r; off += STG_XLO; }
        else if (tile == 2) { g = g_Whi; grow = block_n + r; off += STG_WHI; }
        else                { g = g_Wlo; grow = block_n + r; off += STG_WLO; }
        cp_src[i] = g + (size_t)grow * K_DIM + c16 * 8;
        cp_dst[i] = sbase + off;
    }

    // ---- ldmatrix address components ----
    const int a_row = wm * 32 + (lane & 7) + ((lane >> 3) & 1) * 8;
    const uint32_t a_swz = (uint32_t)((a_row & 7) * 16);
    const int a_khalf = ((lane >> 4) & 1) * 16;
    const int b_row = wn * 32 + (lane & 7) + ((lane >> 4) & 1) * 8;
    const uint32_t b_swz = (uint32_t)((b_row & 7) * 16);
    const int b_khalf = ((lane >> 3) & 1) * 16;

    float acc[2][4][4];
    #pragma unroll
    for (int mf = 0; mf < 2; mf++)
        #pragma unroll
        for (int nf = 0; nf < 4; nf++)
            #pragma unroll
            for (int r = 0; r < 4; r++)
                acc[mf][nf][r] = 0.0f;

    // prologue: stage 0
    #pragma unroll
    for (int i = 0; i < 8; i++) CP_ASYNC16(cp_dst[i], cp_src[i]);
    CP_COMMIT();

    for (int c = 0; c < NCHUNK; c++) {
        if (c + 1 < NCHUNK) {
            const uint32_t stg = (uint32_t)(((c + 1) & 1) * STAGE_BYTES);
            const int koff = (c + 1) * BK;
            #pragma unroll
            for (int i = 0; i < 8; i++) CP_ASYNC16(cp_dst[i] + stg, cp_src[i] + koff);
            CP_COMMIT();
            CP_WAIT1();
        } else {
            CP_WAIT0();
        }
        __syncthreads();

        const uint32_t buf = sbase + (uint32_t)((c & 1) * STAGE_BYTES);

        #pragma unroll
        for (int ks = 0; ks < 4; ks++) {
            uint32_t ahi[2][4], alo[2][4], bhi[4][2], blo[4][2];
            const uint32_t akb = (uint32_t)(ks * 32 + a_khalf) ^ a_swz;
            const uint32_t bkb = (uint32_t)(ks * 32 + b_khalf) ^ b_swz;
            #pragma unroll
            for (int mf = 0; mf < 2; mf++) {
                const uint32_t ao = (uint32_t)((a_row + mf * 16) * 128) + akb;
                LDSM_X4(ahi[mf][0], ahi[mf][1], ahi[mf][2], ahi[mf][3], buf + STG_XHI + ao);
                LDSM_X4(alo[mf][0], alo[mf][1], alo[mf][2], alo[mf][3], buf + STG_XLO + ao);
            }
            #pragma unroll
            for (int np = 0; np < 2; np++) {
                const uint32_t bo = (uint32_t)((b_row + np * 16) * 128) + bkb;
                LDSM_X4(bhi[np * 2][0], bhi[np * 2][1], bhi[np * 2 + 1][0], bhi[np * 2 + 1][1],
                        buf + STG_WHI + bo);
                LDSM_X4(blo[np * 2][0], blo[np * 2][1], blo[np * 2 + 1][0], blo[np * 2 + 1][1],
                        buf + STG_WLO + bo);
            }
            #pragma unroll
            for (int mf = 0; mf < 2; mf++)
                #pragma unroll
                for (int nf = 0; nf < 4; nf++) {
                    MMA_BF16(acc[mf][nf], ahi[mf], bhi[nf]);
                    MMA_BF16(acc[mf][nf], ahi[mf], blo[nf]);
                    MMA_BF16(acc[mf][nf], alo[mf], bhi[nf]);
                }
        }
        __syncthreads();
    }

    // ---- epilogue: direct global stores + bias ----
    const int mrow = block_m + wm * 32 + (lane >> 2);
    const int ncol = block_n + wn * 32 + 2 * (lane & 3);
    #pragma unroll
    for (int mf = 0; mf < 2; mf++) {
        #pragma unroll
        for (int nf = 0; nf < 4; nf++) {
            const int n = ncol + nf * 8;
            const float2 bv = *(const float2*)&bias[n];
            const int r0 = mrow + mf * 16;
            float2 o0 = make_float2(acc[mf][nf][0] + bv.x, acc[mf][nf][1] + bv.y);
            float2 o1 = make_float2(acc[mf][nf][2] + bv.x, acc[mf][nf][3] + bv.y);
            *(float2*)&Out[(size_t)r0 * N_DIM + n] = o0;
            *(float2*)&Out[(size_t)(r0 + 8) * N_DIM + n] = o1;
        }
    }
}

// ---------------------------------------------------------------------------
extern "C" void kernel_launch(void* const* d_in, const int* in_sizes, int n_in,
                              void* d_out, int out_size) {
    const float* x  = (const float*)d_in[0];
    const float* W  = (const float*)d_in[1];
    const float* b  = (const float*)d_in[2];
    const float* A  = (const float*)d_in[3];
    const float* Bm = (const float*)d_in[4];
    float* out = (float*)d_out;

    cudaFuncSetAttribute(lora_gemm_mma_kernel,
                         cudaFuncAttributeMaxDynamicSharedMemorySize, SMEM_BYTES);

    build_weff_split_kernel<<<N_DIM, 256>>>(W, A, Bm);
    split_x_kernel<<<(M_TOTAL * K_DIM) / (256 * 4), 256>>>(x);

    dim3 grid(N_DIM / BN, M_TOTAL / BM);   // (8, 128)
    lora_gemm_mma_kernel<<<grid, 512, SMEM_BYTES>>>(b, out);
}